// round 1
// baseline (speedup 1.0000x reference)
#include <cuda_runtime.h>
#include <math.h>
#include <stdint.h>

// Problem constants
#define BB 4
#define SS 1024
#define DD 768
#define HH 12
#define DH 64
#define NOPE 32
#define ROPE_D 32
#define QP 384
#define KVP 512
#define KVIN 544            // KVP + ROPE
#define KVOUT 1152          // D + H*NOPE
#define EE 8
#define TOPK 2
#define NS 2
#define FF 3072
#define TT (BB*SS)          // 4096 tokens

// ---------------- scratch (static device memory; no allocation) ----------------
__device__ float g_h[TT*DD];
__device__ float g_cq[TT*QP];
__device__ float g_Q[TT*DD];
__device__ float g_ckv[TT*KVIN];
__device__ float g_kvl[TT*KVP];
__device__ float g_KV[TT*KVOUT];
__device__ float g_q[BB*HH*SS*DH];
__device__ float g_k[BB*HH*SS*DH];
__device__ float g_v[BB*HH*SS*DH];
__device__ float g_o[TT*DD];
__device__ float g_h2[TT*DD];
__device__ float g_act[TT*FF];
__device__ float g_contrib[2*TT*DD];
__device__ int   g_cnt[EE];
__device__ int   g_tok[EE*TT];
__device__ int   g_cidx[EE*TT];
__device__ float g_wl[EE*TT];

// ---------------- helpers ----------------
__device__ __forceinline__ float block_reduce_sum(float v, float* sh) {
    __syncthreads();
    int lane = threadIdx.x & 31, wid = threadIdx.x >> 5;
    #pragma unroll
    for (int o = 16; o; o >>= 1) v += __shfl_down_sync(0xffffffffu, v, o);
    if (lane == 0) sh[wid] = v;
    __syncthreads();
    if (threadIdx.x == 0) {
        float r = 0.f;
        int nw = blockDim.x >> 5;
        for (int i = 0; i < nw; i++) r += sh[i];
        sh[0] = r;
    }
    __syncthreads();
    return sh[0];
}

__device__ __forceinline__ float block_reduce_max(float v, float* sh) {
    __syncthreads();
    int lane = threadIdx.x & 31, wid = threadIdx.x >> 5;
    #pragma unroll
    for (int o = 16; o; o >>= 1) v = fmaxf(v, __shfl_down_sync(0xffffffffu, v, o));
    if (lane == 0) sh[wid] = v;
    __syncthreads();
    if (threadIdx.x == 0) {
        float r = sh[0];
        int nw = blockDim.x >> 5;
        for (int i = 1; i < nw; i++) r = fmaxf(r, sh[i]);
        sh[0] = r;
    }
    __syncthreads();
    return sh[0];
}

// ---------------- LayerNorm ----------------
__global__ void ln_kernel(const float* __restrict__ x, const float* __restrict__ w,
                          const float* __restrict__ b, float* __restrict__ y,
                          int cols, int inStride, int outStride) {
    int row = blockIdx.x;
    const float* xi = x + (size_t)row * inStride;
    float* yo = y + (size_t)row * outStride;
    __shared__ float sh[8];
    int t = threadIdx.x;
    float s = 0.f;
    for (int j = t; j < cols; j += 256) s += xi[j];
    float mean = block_reduce_sum(s, sh) / (float)cols;
    float v = 0.f;
    for (int j = t; j < cols; j += 256) { float d = xi[j] - mean; v += d * d; }
    float var = block_reduce_sum(v, sh) / (float)cols;
    float rstd = rsqrtf(var + 1e-5f);
    for (int j = t; j < cols; j += 256) {
        float o = (xi[j] - mean) * rstd * w[j];
        if (b) o += b[j];
        yo[j] = o;
    }
}

// ---------------- GEMM (C = A[MxK] * B[KxN]) ----------------
__global__ void gemm_nn(const float* __restrict__ A, const float* __restrict__ Bm,
                        float* __restrict__ C, int M, int N, int K) {
    __shared__ float As[16][65];
    __shared__ float Bs[16][65];
    int bm = blockIdx.y * 64, bn = blockIdx.x * 64;
    int t = threadIdx.x;
    int tx = t & 15, ty = t >> 4;
    float acc[4][4] = {};
    for (int k0 = 0; k0 < K; k0 += 16) {
        #pragma unroll
        for (int rr = 0; rr < 4; rr++) {
            int r = (t >> 4) + rr * 16;
            int c = t & 15;
            int gm = bm + r;
            As[c][r] = (gm < M) ? A[(size_t)gm * K + k0 + c] : 0.f;
        }
        #pragma unroll
        for (int rr = 0; rr < 4; rr++) {
            int k = (t >> 6) + rr * 4;
            int n = t & 63;
            int gn = bn + n;
            Bs[k][n] = (gn < N) ? Bm[(size_t)(k0 + k) * N + gn] : 0.f;
        }
        __syncthreads();
        #pragma unroll
        for (int k = 0; k < 16; k++) {
            float a[4], b[4];
            #pragma unroll
            for (int i = 0; i < 4; i++) a[i] = As[k][ty * 4 + i];
            #pragma unroll
            for (int j = 0; j < 4; j++) b[j] = Bs[k][tx * 4 + j];
            #pragma unroll
            for (int i = 0; i < 4; i++)
                #pragma unroll
                for (int j = 0; j < 4; j++) acc[i][j] += a[i] * b[j];
        }
        __syncthreads();
    }
    #pragma unroll
    for (int i = 0; i < 4; i++) {
        int m = bm + ty * 4 + i;
        if (m >= M) continue;
        #pragma unroll
        for (int j = 0; j < 4; j++) {
            int n = bn + tx * 4 + j;
            if (n >= N) continue;
            C[(size_t)m * N + n] = acc[i][j];
        }
    }
}

// ---------------- GEMM (C = A[MxK] * B[NxK]^T) with epilogue options ----------------
__global__ void gemm_nt(const float* __restrict__ A, const float* __restrict__ Bm,
                        float* __restrict__ C, int M, int N, int K,
                        const float* __restrict__ resid, int doGelu, int doAccum,
                        const int* __restrict__ aRows, const int* __restrict__ cRows,
                        const float* __restrict__ rowScale, const int* __restrict__ cntPtr) {
    __shared__ float As[16][65];
    __shared__ float Bs[16][65];
    int Meff = M;
    if (cntPtr) { int c = *cntPtr; if (c < Meff) Meff = c; }
    int bm = blockIdx.y * 64, bn = blockIdx.x * 64;
    if (bm >= Meff) return;
    int t = threadIdx.x;
    int tx = t & 15, ty = t >> 4;
    float acc[4][4] = {};
    for (int k0 = 0; k0 < K; k0 += 16) {
        #pragma unroll
        for (int rr = 0; rr < 4; rr++) {
            int r = (t >> 4) + rr * 16;
            int c = t & 15;
            int gm = bm + r;
            float v = 0.f;
            if (gm < Meff) {
                int ar = aRows ? aRows[gm] : gm;
                v = A[(size_t)ar * K + k0 + c];
            }
            As[c][r] = v;
        }
        #pragma unroll
        for (int rr = 0; rr < 4; rr++) {
            int n = (t >> 4) + rr * 16;
            int c = t & 15;
            int gn = bn + n;
            Bs[c][n] = (gn < N) ? Bm[(size_t)gn * K + k0 + c] : 0.f;
        }
        __syncthreads();
        #pragma unroll
        for (int k = 0; k < 16; k++) {
            float a[4], b[4];
            #pragma unroll
            for (int i = 0; i < 4; i++) a[i] = As[k][ty * 4 + i];
            #pragma unroll
            for (int j = 0; j < 4; j++) b[j] = Bs[k][tx * 4 + j];
            #pragma unroll
            for (int i = 0; i < 4; i++)
                #pragma unroll
                for (int j = 0; j < 4; j++) acc[i][j] += a[i] * b[j];
        }
        __syncthreads();
    }
    #pragma unroll
    for (int i = 0; i < 4; i++) {
        int m = bm + ty * 4 + i;
        if (m >= Meff) continue;
        float scale = rowScale ? rowScale[m] : 1.f;
        int crow = cRows ? cRows[m] : m;
        #pragma unroll
        for (int j = 0; j < 4; j++) {
            int n = bn + tx * 4 + j;
            if (n >= N) continue;
            float v = acc[i][j];
            if (doGelu) v = 0.5f * v * (1.f + erff(v * 0.70710678118654752f));
            v *= scale;
            if (resid) v += resid[(size_t)m * N + n];
            size_t oidx = (size_t)crow * N + n;
            if (doAccum) C[oidx] += v; else C[oidx] = v;
        }
    }
}

// ---------------- build q/k/v with RoPE ----------------
__global__ void qkv_build() {
    int s = blockIdx.x, h = blockIdx.y, b = blockIdx.z, d = threadIdx.x;
    int i = b * SS + s;
    __shared__ float qr[32], kr[32];
    if (d < 32) {
        qr[d] = g_Q[(size_t)i * DD + h * DH + NOPE + d];
        kr[d] = g_ckv[(size_t)i * KVIN + KVP + d];
    }
    __syncthreads();
    float qv, kv;
    if (d < NOPE) {
        qv = g_Q[(size_t)i * DD + h * DH + d];
        kv = g_KV[(size_t)i * KVOUT + h * 96 + d];
    } else {
        int j = d - NOPE;
        int fi = j & 15;
        float ang = (float)s * expf(-(float)fi * (9.210340371976184f / 32.f));
        float c = cosf(ang), sn = sinf(ang);
        float qrot = (j < 16) ? -qr[j + 16] : qr[j - 16];
        float krot = (j < 16) ? -kr[j + 16] : kr[j - 16];
        qv = qr[j] * c + qrot * sn;
        kv = kr[j] * c + krot * sn;
    }
    size_t o = (((size_t)b * HH + h) * SS + s) * DH + d;
    g_q[o] = qv;
    g_k[o] = kv;
    g_v[o] = g_KV[(size_t)i * KVOUT + h * 96 + NOPE + d];
}

// ---------------- causal attention (one block per query row) ----------------
__global__ void attn_kernel() {
    int s = blockIdx.x, h = blockIdx.y, b = blockIdx.z;
    __shared__ float qs[64];
    __shared__ float p[SS];
    __shared__ float sh[8];
    __shared__ float ov[64];
    int t = threadIdx.x;  // 128
    const float* qptr = g_q + (((size_t)b * HH + h) * SS + s) * DH;
    if (t < 64) qs[t] = qptr[t];
    __syncthreads();
    int nk = s + 1;
    const float* kbase = g_k + (((size_t)b * HH + h) * SS) * DH;
    float lmax = -1e30f;
    for (int kt = t; kt < nk; kt += 128) {
        const float4* kp = (const float4*)(kbase + (size_t)kt * DH);
        const float4* qf = (const float4*)qs;
        float dsum = 0.f;
        #pragma unroll
        for (int j = 0; j < 16; j++) {
            float4 kvv = kp[j];
            float4 qvv = qf[j];
            dsum += qvv.x * kvv.x + qvv.y * kvv.y + qvv.z * kvv.z + qvv.w * kvv.w;
        }
        dsum *= 0.125f;
        p[kt] = dsum;
        lmax = fmaxf(lmax, dsum);
    }
    float mx = block_reduce_max(lmax, sh);
    float lsum = 0.f;
    for (int kt = t; kt < nk; kt += 128) {
        float e = expf(p[kt] - mx);
        p[kt] = e;
        lsum += e;
    }
    float sum = block_reduce_sum(lsum, sh);
    const float* vbase = g_v + (((size_t)b * HH + h) * SS) * DH;
    int d = t & 63, half = t >> 6;
    float part = 0.f;
    for (int kt = half; kt < nk; kt += 2) part += p[kt] * vbase[(size_t)kt * DH + d];
    if (half == 1) ov[d] = part;
    __syncthreads();
    if (half == 0) {
        float o = (part + ov[d]) / sum;
        g_o[((size_t)(b * SS + s)) * DD + h * DH + d] = o;
    }
}

// ---------------- routing: sigmoid gates, top-2, expert list build ----------------
__global__ void zero_cnt_kernel() {
    if (threadIdx.x < EE) g_cnt[threadIdx.x] = 0;
}

__global__ void route_kernel(const float* __restrict__ h2, const float* __restrict__ cent,
                             const float* __restrict__ rbias) {
    int warp = threadIdx.x >> 5, lane = threadIdx.x & 31;
    int tok = blockIdx.x * 8 + warp;
    if (tok >= TT) return;
    const float* hp = h2 + (size_t)tok * DD;
    float raw[EE];
    #pragma unroll
    for (int e = 0; e < EE; e++) {
        const float* cp = cent + e * DD;
        float s = 0.f;
        for (int j = lane; j < DD; j += 32) s += hp[j] * cp[j];
        #pragma unroll
        for (int o = 16; o; o >>= 1) s += __shfl_down_sync(0xffffffffu, s, o);
        raw[e] = __shfl_sync(0xffffffffu, s, 0);
    }
    if (lane == 0) {
        int e0 = 0;
        float b0 = raw[0] + rbias[0];
        for (int e = 1; e < EE; e++) {
            float v = raw[e] + rbias[e];
            if (v > b0) { b0 = v; e0 = e; }
        }
        int e1 = -1;
        float b1 = -3.4e38f;
        for (int e = 0; e < EE; e++) {
            if (e == e0) continue;
            float v = raw[e] + rbias[e];
            if (v > b1) { b1 = v; e1 = e; }
        }
        float w0 = 1.f / (1.f + expf(-raw[e0]));
        float w1 = 1.f / (1.f + expf(-raw[e1]));
        float inv = 1.f / (w0 + w1 + 1e-9f);
        w0 *= inv; w1 *= inv;
        int p0 = atomicAdd(&g_cnt[e0], 1);
        g_tok[e0 * TT + p0] = tok;
        g_cidx[e0 * TT + p0] = tok;          // slot 0 -> contrib row = tok
        g_wl[e0 * TT + p0] = w0;
        int p1 = atomicAdd(&g_cnt[e1], 1);
        g_tok[e1 * TT + p1] = tok;
        g_cidx[e1 * TT + p1] = TT + tok;     // slot 1 -> contrib row = TT + tok
        g_wl[e1 * TT + p1] = w1;
    }
}

// ---------------- final: out += contrib0 + contrib1 ----------------
__global__ void final_add_kernel(float* __restrict__ out) {
    int idx = blockIdx.x * blockDim.x + threadIdx.x;
    if (idx < TT * DD) out[idx] += g_contrib[idx] + g_contrib[(size_t)TT * DD + idx];
}

// ---------------- launch ----------------
static inline dim3 ggrid(int M, int N) { return dim3((N + 63) / 64, (M + 63) / 64); }

extern "C" void kernel_launch(void* const* d_in, const int* in_sizes, int n_in,
                              void* d_out, int out_size) {
    const float* x        = (const float*)d_in[0];
    const float* ln1_w    = (const float*)d_in[1];
    const float* ln2_w    = (const float*)d_in[2];
    const float* W_dq     = (const float*)d_in[3];
    const float* W_uq     = (const float*)d_in[4];
    const float* q_ln_w   = (const float*)d_in[5];
    const float* q_ln_b   = (const float*)d_in[6];
    const float* W_dkv    = (const float*)d_in[7];
    const float* W_ukv    = (const float*)d_in[8];
    const float* kv_ln_w  = (const float*)d_in[9];
    const float* kv_ln_b  = (const float*)d_in[10];
    const float* W_o      = (const float*)d_in[11];
    const float* s_fc     = (const float*)d_in[12];
    const float* s_proj   = (const float*)d_in[13];
    const float* e_fc     = (const float*)d_in[14];
    const float* e_proj   = (const float*)d_in[15];
    const float* centroids= (const float*)d_in[16];
    const float* rbias    = (const float*)d_in[17];
    float* out = (float*)d_out;

    float *ph, *pcq, *pQ, *pckv, *pkvl, *pKV, *po, *ph2, *pact, *pcontrib, *pwl;
    int *pcnt, *ptok, *pcidx;
    cudaGetSymbolAddress((void**)&ph, g_h);
    cudaGetSymbolAddress((void**)&pcq, g_cq);
    cudaGetSymbolAddress((void**)&pQ, g_Q);
    cudaGetSymbolAddress((void**)&pckv, g_ckv);
    cudaGetSymbolAddress((void**)&pkvl, g_kvl);
    cudaGetSymbolAddress((void**)&pKV, g_KV);
    cudaGetSymbolAddress((void**)&po, g_o);
    cudaGetSymbolAddress((void**)&ph2, g_h2);
    cudaGetSymbolAddress((void**)&pact, g_act);
    cudaGetSymbolAddress((void**)&pcontrib, g_contrib);
    cudaGetSymbolAddress((void**)&pwl, g_wl);
    cudaGetSymbolAddress((void**)&pcnt, g_cnt);
    cudaGetSymbolAddress((void**)&ptok, g_tok);
    cudaGetSymbolAddress((void**)&pcidx, g_cidx);

    // 1) h = LN1(x)
    ln_kernel<<<TT, 256>>>(x, ln1_w, nullptr, ph, DD, DD, DD);
    // 2) cq = LN_q(h @ W_dq)
    gemm_nn<<<ggrid(TT, QP), 256>>>(ph, W_dq, pcq, TT, QP, DD);
    ln_kernel<<<TT, 256>>>(pcq, q_ln_w, q_ln_b, pcq, QP, QP, QP);
    // 3) Q = cq @ W_uq
    gemm_nn<<<ggrid(TT, DD), 256>>>(pcq, W_uq, pQ, TT, DD, QP);
    // 4) ckv = h @ W_dkv ; kv_lora = LN_kv(ckv[:, :512])
    gemm_nn<<<ggrid(TT, KVIN), 256>>>(ph, W_dkv, pckv, TT, KVIN, DD);
    ln_kernel<<<TT, 256>>>(pckv, kv_ln_w, kv_ln_b, pkvl, KVP, KVIN, KVP);
    // 5) KV = kv_lora @ W_ukv
    gemm_nn<<<ggrid(TT, KVOUT), 256>>>(pkvl, W_ukv, pKV, TT, KVOUT, KVP);
    // 6) q/k/v with RoPE
    qkv_build<<<dim3(SS, HH, BB), 64>>>();
    // 7) attention -> g_o
    attn_kernel<<<dim3(SS, HH, BB), 128>>>();
    // 8) out = x + o @ W_o^T
    gemm_nt<<<ggrid(TT, DD), 256>>>(po, W_o, out, TT, DD, DD,
                                    x, 0, 0, nullptr, nullptr, nullptr, nullptr);
    // 9) h2 = LN2(out)
    ln_kernel<<<TT, 256>>>(out, ln2_w, nullptr, ph2, DD, DD, DD);
    // 10) routing + expert list build
    zero_cnt_kernel<<<1, 32>>>();
    route_kernel<<<(TT + 7) / 8, 256>>>(ph2, centroids, rbias);
    // 11) shared experts: out += gelu(h2 @ s_fc[n]^T) @ s_proj[n]^T
    for (int n = 0; n < NS; n++) {
        gemm_nt<<<ggrid(TT, FF), 256>>>(ph2, s_fc + (size_t)n * FF * DD, pact, TT, FF, DD,
                                        nullptr, 1, 0, nullptr, nullptr, nullptr, nullptr);
        gemm_nt<<<ggrid(TT, DD), 256>>>(pact, s_proj + (size_t)n * DD * FF, out, TT, DD, FF,
                                        nullptr, 0, 1, nullptr, nullptr, nullptr, nullptr);
    }
    // 12) routed experts (gathered, count-bounded)
    for (int e = 0; e < EE; e++) {
        gemm_nt<<<ggrid(TT, FF), 256>>>(ph2, e_fc + (size_t)e * FF * DD, pact, TT, FF, DD,
                                        nullptr, 1, 0, ptok + e * TT, nullptr, nullptr, pcnt + e);
        gemm_nt<<<ggrid(TT, DD), 256>>>(pact, e_proj + (size_t)e * DD * FF, pcontrib, TT, DD, FF,
                                        nullptr, 0, 0, nullptr, pcidx + e * TT, pwl + e * TT, pcnt + e);
    }
    // 13) out += contrib(slot0) + contrib(slot1)
    final_add_kernel<<<(TT * DD + 255) / 256, 256>>>(out);
}

// round 5
// speedup vs baseline: 2.2258x; 2.2258x over previous
#include <cuda_runtime.h>
#include <math.h>
#include <stdint.h>

// Problem constants
#define BB 4
#define SS 1024
#define DD 768
#define HH 12
#define DH 64
#define NOPE 32
#define QP 384
#define KVP 512
#define KVIN 544            // KVP + ROPE
#define KVOUT 1152          // D + H*NOPE
#define EE 8
#define NS 2
#define FF 3072
#define TT (BB*SS)          // 4096 tokens

#define BM 128
#define BN 128
#define BK 32

// ---------------- scratch ----------------
__device__ float g_h[TT*DD];
__device__ float g_cq[TT*QP];
__device__ float g_Q[TT*DD];
__device__ float g_ckv[TT*KVIN];
__device__ float g_kvl[TT*KVP];
__device__ float g_KV[TT*KVOUT];
__device__ float g_qq[BB*HH*SS*DH];
__device__ float g_kk[BB*HH*SS*DH];
__device__ float g_vv[BB*HH*SS*DH];
__device__ float g_o[TT*DD];
__device__ float g_h2[TT*DD];
__device__ float g_act[TT*FF];
__device__ float g_contrib[2*TT*DD];
__device__ int   g_cnt[EE];
__device__ int   g_tok[EE*TT];
__device__ int   g_cidx[EE*TT];
__device__ float g_wl[EE*TT];

__device__ __forceinline__ uint32_t f2tf32(float f) {
    uint32_t r;
    asm("cvt.rna.tf32.f32 %0, %1;" : "=r"(r) : "f"(f));
    return r;
}

__device__ __forceinline__ void mma_tf32(float c[4], const uint32_t a[4], const uint32_t b[2]) {
    asm volatile("mma.sync.aligned.m16n8k8.row.col.f32.tf32.tf32.f32 "
                 "{%0,%1,%2,%3}, {%4,%5,%6,%7}, {%8,%9}, {%0,%1,%2,%3};"
                 : "+f"(c[0]), "+f"(c[1]), "+f"(c[2]), "+f"(c[3])
                 : "r"(a[0]), "r"(a[1]), "r"(a[2]), "r"(a[3]), "r"(b[0]), "r"(b[1]));
}

// ---------------- block reduce helpers ----------------
__device__ __forceinline__ float block_reduce_sum(float v, float* sh) {
    __syncthreads();
    int lane = threadIdx.x & 31, wid = threadIdx.x >> 5;
    #pragma unroll
    for (int o = 16; o; o >>= 1) v += __shfl_down_sync(0xffffffffu, v, o);
    if (lane == 0) sh[wid] = v;
    __syncthreads();
    if (threadIdx.x == 0) {
        float r = 0.f;
        int nw = blockDim.x >> 5;
        for (int i = 0; i < nw; i++) r += sh[i];
        sh[0] = r;
    }
    __syncthreads();
    return sh[0];
}

// ---------------- LayerNorm ----------------
__global__ void ln_kernel(const float* __restrict__ x, const float* __restrict__ w,
                          const float* __restrict__ b, float* __restrict__ y,
                          int cols, int inStride, int outStride) {
    int row = blockIdx.x;
    const float* xi = x + (size_t)row * inStride;
    float* yo = y + (size_t)row * outStride;
    __shared__ float sh[8];
    int t = threadIdx.x;
    float s = 0.f;
    for (int j = t; j < cols; j += 256) s += xi[j];
    float mean = block_reduce_sum(s, sh) / (float)cols;
    float v = 0.f;
    for (int j = t; j < cols; j += 256) { float d = xi[j] - mean; v += d * d; }
    float var = block_reduce_sum(v, sh) / (float)cols;
    float rstd = rsqrtf(var + 1e-5f);
    for (int j = t; j < cols; j += 256) {
        float o = (xi[j] - mean) * rstd * w[j];
        if (b) o += b[j];
        yo[j] = o;
    }
}

// ---------------- TF32 tensor-core GEMM ----------------
// C[M,N] = A[M,K] @ B  where B is [K,N] (BisNT=0) or [N,K]^T (BisNT=1)
// Optional: row gather (aRows), row scatter (cRows), per-row scale, gelu,
// residual add, accumulate, dynamic M bound (*cntPtr).
__global__ void __launch_bounds__(256)
gemm_tf32(const float* __restrict__ A, const float* __restrict__ Bm, float* __restrict__ C,
          int M, int N, int K, int BisNT,
          const float* __restrict__ resid, int doGelu, int doAccum,
          const int* __restrict__ aRows, const int* __restrict__ cRows,
          const float* __restrict__ rowScale, const int* __restrict__ cntPtr) {
    __shared__ uint32_t As[BK][BM + 8];
    __shared__ uint32_t Bs[BK][BN + 8];
    int Meff = M;
    if (cntPtr) { int c = *cntPtr; if (c < Meff) Meff = c; }
    int bm = blockIdx.y * BM, bn = blockIdx.x * BN;
    if (bm >= Meff) return;
    int t = threadIdx.x;
    int lane = t & 31, warp = t >> 5;
    int wm = warp & 1, wn = warp >> 1;       // 2 x 4 warp grid
    int g = lane >> 2, tg = lane & 3;
    float acc[4][4][4];
    #pragma unroll
    for (int a = 0; a < 4; a++)
        #pragma unroll
        for (int b = 0; b < 4; b++)
            #pragma unroll
            for (int c = 0; c < 4; c++) acc[a][b][c] = 0.f;

    for (int k0 = 0; k0 < K; k0 += BK) {
        // --- stage A (transposed to [k][m], tf32) ---
        {
            int kq = t & 7, r0 = t >> 3;
            #pragma unroll
            for (int it = 0; it < 4; it++) {
                int r = r0 + it * 32;
                int gm = bm + r;
                float4 v = make_float4(0.f, 0.f, 0.f, 0.f);
                if (gm < Meff) {
                    int ar = aRows ? aRows[gm] : gm;
                    v = *(const float4*)(A + (size_t)ar * K + k0 + kq * 4);
                }
                As[kq * 4 + 0][r] = f2tf32(v.x);
                As[kq * 4 + 1][r] = f2tf32(v.y);
                As[kq * 4 + 2][r] = f2tf32(v.z);
                As[kq * 4 + 3][r] = f2tf32(v.w);
            }
        }
        // --- stage B as [k][n], tf32 ---
        if (!BisNT) {
            int nq = t & 31, kr = t >> 5;
            #pragma unroll
            for (int it = 0; it < 4; it++) {
                int k = kr + it * 8;
                int gn0 = bn + nq * 4;
                if (gn0 + 3 < N) {
                    float4 v = *(const float4*)(Bm + (size_t)(k0 + k) * N + gn0);
                    Bs[k][nq * 4 + 0] = f2tf32(v.x);
                    Bs[k][nq * 4 + 1] = f2tf32(v.y);
                    Bs[k][nq * 4 + 2] = f2tf32(v.z);
                    Bs[k][nq * 4 + 3] = f2tf32(v.w);
                } else {
                    #pragma unroll
                    for (int c = 0; c < 4; c++) {
                        int gn = gn0 + c;
                        Bs[k][nq * 4 + c] = (gn < N) ? f2tf32(Bm[(size_t)(k0 + k) * N + gn]) : 0u;
                    }
                }
            }
        } else {
            int kq = t & 7, n0 = t >> 3;
            #pragma unroll
            for (int it = 0; it < 4; it++) {
                int n = n0 + it * 32;
                int gn = bn + n;
                float4 v = make_float4(0.f, 0.f, 0.f, 0.f);
                if (gn < N) v = *(const float4*)(Bm + (size_t)gn * K + k0 + kq * 4);
                Bs[kq * 4 + 0][n] = f2tf32(v.x);
                Bs[kq * 4 + 1][n] = f2tf32(v.y);
                Bs[kq * 4 + 2][n] = f2tf32(v.z);
                Bs[kq * 4 + 3][n] = f2tf32(v.w);
            }
        }
        __syncthreads();
        // --- mma ---
        #pragma unroll
        for (int ks = 0; ks < 4; ks++) {
            int kb = ks * 8;
            uint32_t afr[4][4], bfr[4][2];
            #pragma unroll
            for (int mi = 0; mi < 4; mi++) {
                int mr = wm * 64 + mi * 16;
                afr[mi][0] = As[kb + tg][mr + g];
                afr[mi][1] = As[kb + tg][mr + g + 8];
                afr[mi][2] = As[kb + tg + 4][mr + g];
                afr[mi][3] = As[kb + tg + 4][mr + g + 8];
            }
            #pragma unroll
            for (int ni = 0; ni < 4; ni++) {
                int nc = wn * 32 + ni * 8;
                bfr[ni][0] = Bs[kb + tg][nc + g];
                bfr[ni][1] = Bs[kb + tg + 4][nc + g];
            }
            #pragma unroll
            for (int mi = 0; mi < 4; mi++)
                #pragma unroll
                for (int ni = 0; ni < 4; ni++)
                    mma_tf32(acc[mi][ni], afr[mi], bfr[ni]);
        }
        __syncthreads();
    }
    // --- epilogue ---
    #pragma unroll
    for (int mi = 0; mi < 4; mi++) {
        #pragma unroll
        for (int hh = 0; hh < 2; hh++) {
            int m = bm + wm * 64 + mi * 16 + g + hh * 8;
            if (m >= Meff) continue;
            float scale = rowScale ? rowScale[m] : 1.f;
            int crow = cRows ? cRows[m] : m;
            #pragma unroll
            for (int ni = 0; ni < 4; ni++) {
                #pragma unroll
                for (int jj = 0; jj < 2; jj++) {
                    int col = bn + wn * 32 + ni * 8 + tg * 2 + jj;
                    if (col >= N) continue;
                    float v = acc[mi][ni][hh * 2 + jj];
                    if (doGelu) v = 0.5f * v * (1.f + erff(v * 0.70710678118654752f));
                    v *= scale;
                    if (resid) v += resid[(size_t)m * N + col];
                    size_t oidx = (size_t)crow * N + col;
                    if (doAccum) C[oidx] += v; else C[oidx] = v;
                }
            }
        }
    }
}

// ---------------- build q/k/v with RoPE ----------------
__global__ void qkv_build() {
    int s = blockIdx.x, h = blockIdx.y, b = blockIdx.z, d = threadIdx.x;
    int i = b * SS + s;
    __shared__ float qr[32], kr[32];
    if (d < 32) {
        qr[d] = g_Q[(size_t)i * DD + h * DH + NOPE + d];
        kr[d] = g_ckv[(size_t)i * KVIN + KVP + d];
    }
    __syncthreads();
    float qv, kv;
    if (d < NOPE) {
        qv = g_Q[(size_t)i * DD + h * DH + d];
        kv = g_KV[(size_t)i * KVOUT + h * 96 + d];
    } else {
        int j = d - NOPE;
        int fi = j & 15;
        float ang = (float)s * expf(-(float)fi * (9.210340371976184f / 32.f));
        float c = cosf(ang), sn = sinf(ang);
        float qrot = (j < 16) ? -qr[j + 16] : qr[j - 16];
        float krot = (j < 16) ? -kr[j + 16] : kr[j - 16];
        qv = qr[j] * c + qrot * sn;
        kv = kr[j] * c + krot * sn;
    }
    size_t o = (((size_t)b * HH + h) * SS + s) * DH + d;
    g_qq[o] = qv;
    g_kk[o] = kv;
    g_vv[o] = g_KV[(size_t)i * KVOUT + h * 96 + NOPE + d];
}

// ---------------- flash attention: 64 queries per block ----------------
__global__ void __launch_bounds__(256) flash_attn() {
    int qt = blockIdx.x, h = blockIdx.y, b = blockIdx.z;
    int t = threadIdx.x;
    int tx = t & 15, ty = t >> 4;
    __shared__ float Qst[64][64];    // [d][m], pre-scaled
    __shared__ float KP[64][72];     // Kst [d][n]  -> then Ps [m][kk]
    const size_t bh = ((size_t)b * HH + h) * SS;
    const float* qg = g_qq + (bh + (size_t)qt * 64) * DH;
    {
        int m = t & 63, c0 = t >> 6;
        #pragma unroll
        for (int it = 0; it < 4; it++) {
            int d4 = c0 + it * 4;
            float4 v = *(const float4*)(qg + (size_t)m * DH + d4 * 4);
            Qst[d4 * 4 + 0][m] = v.x * 0.125f;
            Qst[d4 * 4 + 1][m] = v.y * 0.125f;
            Qst[d4 * 4 + 2][m] = v.z * 0.125f;
            Qst[d4 * 4 + 3][m] = v.w * 0.125f;
        }
    }
    float accO[4][4];
    float rowM[4], rowL[4];
    #pragma unroll
    for (int i = 0; i < 4; i++) {
        rowM[i] = -1e30f; rowL[i] = 0.f;
        #pragma unroll
        for (int j = 0; j < 4; j++) accO[i][j] = 0.f;
    }
    for (int kt = 0; kt <= qt; kt++) {
        const float* kg = g_kk + (bh + (size_t)kt * 64) * DH;
        __syncthreads();  // prior PV reads of KP done
        {
            int n = t & 63, c0 = t >> 6;
            #pragma unroll
            for (int it = 0; it < 4; it++) {
                int d4 = c0 + it * 4;
                float4 v = *(const float4*)(kg + (size_t)n * DH + d4 * 4);
                KP[d4 * 4 + 0][n] = v.x;
                KP[d4 * 4 + 1][n] = v.y;
                KP[d4 * 4 + 2][n] = v.z;
                KP[d4 * 4 + 3][n] = v.w;
            }
        }
        __syncthreads();
        // S = Q^T K  (64x64 tile), thread owns rows ty*4+i, cols tx*4+j
        float s[4][4];
        #pragma unroll
        for (int i = 0; i < 4; i++)
            #pragma unroll
            for (int j = 0; j < 4; j++) s[i][j] = 0.f;
        #pragma unroll 8
        for (int d = 0; d < 64; d++) {
            float4 qa = *(const float4*)&Qst[d][ty * 4];
            float4 kb = *(const float4*)&KP[d][tx * 4];
            float aa[4] = {qa.x, qa.y, qa.z, qa.w};
            float bb[4] = {kb.x, kb.y, kb.z, kb.w};
            #pragma unroll
            for (int i = 0; i < 4; i++)
                #pragma unroll
                for (int j = 0; j < 4; j++) s[i][j] += aa[i] * bb[j];
        }
        if (kt == qt) {
            #pragma unroll
            for (int i = 0; i < 4; i++)
                #pragma unroll
                for (int j = 0; j < 4; j++)
                    if (tx * 4 + j > ty * 4 + i) s[i][j] = -1e30f;
        }
        float ps[4][4];
        #pragma unroll
        for (int i = 0; i < 4; i++) {
            float tm = fmaxf(fmaxf(s[i][0], s[i][1]), fmaxf(s[i][2], s[i][3]));
            #pragma unroll
            for (int o = 8; o; o >>= 1) tm = fmaxf(tm, __shfl_xor_sync(0xffffffffu, tm, o, 16));
            float nm = fmaxf(rowM[i], tm);
            float corr = __expf(rowM[i] - nm);
            rowM[i] = nm;
            float rs = 0.f;
            #pragma unroll
            for (int j = 0; j < 4; j++) { ps[i][j] = __expf(s[i][j] - nm); rs += ps[i][j]; }
            #pragma unroll
            for (int o = 8; o; o >>= 1) rs += __shfl_xor_sync(0xffffffffu, rs, o, 16);
            rowL[i] = rowL[i] * corr + rs;
            #pragma unroll
            for (int j = 0; j < 4; j++) accO[i][j] *= corr;
        }
        __syncthreads();  // done reading Kst
        #pragma unroll
        for (int i = 0; i < 4; i++)
            *(float4*)&KP[ty * 4 + i][tx * 4] = make_float4(ps[i][0], ps[i][1], ps[i][2], ps[i][3]);
        __syncthreads();
        // O += P V  (V streamed from global/L1)
        const float* vg = g_vv + (bh + (size_t)kt * 64) * DH;
        #pragma unroll 4
        for (int k4 = 0; k4 < 16; k4++) {
            float pav[4][4];
            #pragma unroll
            for (int i = 0; i < 4; i++)
                *(float4*)pav[i] = *(const float4*)&KP[ty * 4 + i][k4 * 4];
            #pragma unroll
            for (int kk = 0; kk < 4; kk++) {
                float4 vb = *(const float4*)(vg + (size_t)(k4 * 4 + kk) * DH + tx * 4);
                float bb[4] = {vb.x, vb.y, vb.z, vb.w};
                #pragma unroll
                for (int i = 0; i < 4; i++)
                    #pragma unroll
                    for (int j = 0; j < 4; j++) accO[i][j] += pav[i][kk] * bb[j];
            }
        }
    }
    #pragma unroll
    for (int i = 0; i < 4; i++) {
        float inv = 1.f / rowL[i];
        int m = qt * 64 + ty * 4 + i;
        float* op = g_o + ((size_t)(b * SS + m)) * DD + h * DH + tx * 4;
        op[0] = accO[i][0] * inv;
        op[1] = accO[i][1] * inv;
        op[2] = accO[i][2] * inv;
        op[3] = accO[i][3] * inv;
    }
}

// ---------------- routing ----------------
__global__ void zero_cnt_kernel() {
    if (threadIdx.x < EE) g_cnt[threadIdx.x] = 0;
}

__global__ void route_kernel(const float* __restrict__ h2, const float* __restrict__ cent,
                             const float* __restrict__ rbias) {
    int warp = threadIdx.x >> 5, lane = threadIdx.x & 31;
    int tok = blockIdx.x * 8 + warp;
    if (tok >= TT) return;
    const float* hp = h2 + (size_t)tok * DD;
    float raw[EE];
    #pragma unroll
    for (int e = 0; e < EE; e++) {
        const float* cp = cent + e * DD;
        float s = 0.f;
        for (int j = lane; j < DD; j += 32) s += hp[j] * cp[j];
        #pragma unroll
        for (int o = 16; o; o >>= 1) s += __shfl_down_sync(0xffffffffu, s, o);
        raw[e] = __shfl_sync(0xffffffffu, s, 0);
    }
    if (lane == 0) {
        int e0 = 0;
        float b0 = raw[0] + rbias[0];
        for (int e = 1; e < EE; e++) {
            float v = raw[e] + rbias[e];
            if (v > b0) { b0 = v; e0 = e; }
        }
        int e1 = -1;
        float b1 = -3.4e38f;
        for (int e = 0; e < EE; e++) {
            if (e == e0) continue;
            float v = raw[e] + rbias[e];
            if (v > b1) { b1 = v; e1 = e; }
        }
        float w0 = 1.f / (1.f + expf(-raw[e0]));
        float w1 = 1.f / (1.f + expf(-raw[e1]));
        float inv = 1.f / (w0 + w1 + 1e-9f);
        w0 *= inv; w1 *= inv;
        int p0 = atomicAdd(&g_cnt[e0], 1);
        g_tok[e0 * TT + p0] = tok;
        g_cidx[e0 * TT + p0] = tok;
        g_wl[e0 * TT + p0] = w0;
        int p1 = atomicAdd(&g_cnt[e1], 1);
        g_tok[e1 * TT + p1] = tok;
        g_cidx[e1 * TT + p1] = TT + tok;
        g_wl[e1 * TT + p1] = w1;
    }
}

__global__ void final_add_kernel(float* __restrict__ out) {
    int idx = blockIdx.x * blockDim.x + threadIdx.x;
    if (idx < TT * DD) out[idx] += g_contrib[idx] + g_contrib[(size_t)TT * DD + idx];
}

// ---------------- launch ----------------
static inline dim3 ggrid(int M, int N) { return dim3((N + BN - 1) / BN, (M + BM - 1) / BM); }

extern "C" void kernel_launch(void* const* d_in, const int* in_sizes, int n_in,
                              void* d_out, int out_size) {
    const float* x        = (const float*)d_in[0];
    const float* ln1_w    = (const float*)d_in[1];
    const float* ln2_w    = (const float*)d_in[2];
    const float* W_dq     = (const float*)d_in[3];
    const float* W_uq     = (const float*)d_in[4];
    const float* q_ln_w   = (const float*)d_in[5];
    const float* q_ln_b   = (const float*)d_in[6];
    const float* W_dkv    = (const float*)d_in[7];
    const float* W_ukv    = (const float*)d_in[8];
    const float* kv_ln_w  = (const float*)d_in[9];
    const float* kv_ln_b  = (const float*)d_in[10];
    const float* W_o      = (const float*)d_in[11];
    const float* s_fc     = (const float*)d_in[12];
    const float* s_proj   = (const float*)d_in[13];
    const float* e_fc     = (const float*)d_in[14];
    const float* e_proj   = (const float*)d_in[15];
    const float* centroids= (const float*)d_in[16];
    const float* rbias    = (const float*)d_in[17];
    float* out = (float*)d_out;

    float *ph, *pcq, *pQ, *pckv, *pkvl, *pKV, *po, *ph2, *pact, *pcontrib, *pwl;
    int *pcnt, *ptok, *pcidx;
    cudaGetSymbolAddress((void**)&ph, g_h);
    cudaGetSymbolAddress((void**)&pcq, g_cq);
    cudaGetSymbolAddress((void**)&pQ, g_Q);
    cudaGetSymbolAddress((void**)&pckv, g_ckv);
    cudaGetSymbolAddress((void**)&pkvl, g_kvl);
    cudaGetSymbolAddress((void**)&pKV, g_KV);
    cudaGetSymbolAddress((void**)&po, g_o);
    cudaGetSymbolAddress((void**)&ph2, g_h2);
    cudaGetSymbolAddress((void**)&pact, g_act);
    cudaGetSymbolAddress((void**)&pcontrib, g_contrib);
    cudaGetSymbolAddress((void**)&pwl, g_wl);
    cudaGetSymbolAddress((void**)&pcnt, g_cnt);
    cudaGetSymbolAddress((void**)&ptok, g_tok);
    cudaGetSymbolAddress((void**)&pcidx, g_cidx);

    // 1) h = LN1(x)
    ln_kernel<<<TT, 256>>>(x, ln1_w, nullptr, ph, DD, DD, DD);
    // 2) cq = LN_q(h @ W_dq)
    gemm_tf32<<<ggrid(TT, QP), 256>>>(ph, W_dq, pcq, TT, QP, DD, 0,
        nullptr, 0, 0, nullptr, nullptr, nullptr, nullptr);
    ln_kernel<<<TT, 256>>>(pcq, q_ln_w, q_ln_b, pcq, QP, QP, QP);
    // 3) Q = cq @ W_uq
    gemm_tf32<<<ggrid(TT, DD), 256>>>(pcq, W_uq, pQ, TT, DD, QP, 0,
        nullptr, 0, 0, nullptr, nullptr, nullptr, nullptr);
    // 4) ckv = h @ W_dkv ; kv_lora = LN_kv(ckv[:, :512])
    gemm_tf32<<<ggrid(TT, KVIN), 256>>>(ph, W_dkv, pckv, TT, KVIN, DD, 0,
        nullptr, 0, 0, nullptr, nullptr, nullptr, nullptr);
    ln_kernel<<<TT, 256>>>(pckv, kv_ln_w, kv_ln_b, pkvl, KVP, KVIN, KVP);
    // 5) KV = kv_lora @ W_ukv
    gemm_tf32<<<ggrid(TT, KVOUT), 256>>>(pkvl, W_ukv, pKV, TT, KVOUT, KVP, 0,
        nullptr, 0, 0, nullptr, nullptr, nullptr, nullptr);
    // 6) q/k/v with RoPE
    qkv_build<<<dim3(SS, HH, BB), 64>>>();
    // 7) flash attention -> g_o
    flash_attn<<<dim3(SS / 64, HH, BB), 256>>>();
    // 8) out = x + o @ W_o^T
    gemm_tf32<<<ggrid(TT, DD), 256>>>(po, W_o, out, TT, DD, DD, 1,
        x, 0, 0, nullptr, nullptr, nullptr, nullptr);
    // 9) h2 = LN2(out)
    ln_kernel<<<TT, 256>>>(out, ln2_w, nullptr, ph2, DD, DD, DD);
    // 10) routing
    zero_cnt_kernel<<<1, 32>>>();
    route_kernel<<<(TT + 7) / 8, 256>>>(ph2, centroids, rbias);
    // 11) shared experts
    for (int n = 0; n < NS; n++) {
        gemm_tf32<<<ggrid(TT, FF), 256>>>(ph2, s_fc + (size_t)n * FF * DD, pact, TT, FF, DD, 1,
            nullptr, 1, 0, nullptr, nullptr, nullptr, nullptr);
        gemm_tf32<<<ggrid(TT, DD), 256>>>(pact, s_proj + (size_t)n * DD * FF, out, TT, DD, FF, 1,
            nullptr, 0, 1, nullptr, nullptr, nullptr, nullptr);
    }
    // 12) routed experts (gathered, count-bounded)
    for (int e = 0; e < EE; e++) {
        gemm_tf32<<<ggrid(TT, FF), 256>>>(ph2, e_fc + (size_t)e * FF * DD, pact, TT, FF, DD, 1,
            nullptr, 1, 0, ptok + e * TT, nullptr, nullptr, pcnt + e);
        gemm_tf32<<<ggrid(TT, DD), 256>>>(pact, e_proj + (size_t)e * DD * FF, pcontrib, TT, DD, FF, 1,
            nullptr, 0, 0, nullptr, pcidx + e * TT, pwl + e * TT, pcnt + e);
    }
    // 13) out += contrib0 + contrib1
    final_add_kernel<<<(TT * DD + 255) / 256, 256>>>(out);
}

// round 7
// speedup vs baseline: 6.2420x; 2.8044x over previous
#include <cuda_runtime.h>
#include <math.h>
#include <stdint.h>

// Problem constants
#define BB 4
#define SS 1024
#define DD 768
#define HH 12
#define DH 64
#define NOPE 32
#define QP 384
#define KVP 512
#define KVIN 544            // KVP + ROPE
#define KVOUT 1152          // D + H*NOPE
#define EE 8
#define NS 2
#define FF 3072
#define TT (BB*SS)          // 4096 tokens

#define BM 128
#define BN 128
#define BK 32
#define NSTAGE 3
// per-stage floats: A = 128*36, B = 128*36 (covers NN 32*136=4352 too)
#define A_FLOATS (BM*36)
#define STAGE_FLOATS (A_FLOATS + 4608)
#define SMEM_BYTES (NSTAGE*STAGE_FLOATS*4)

// ---------------- scratch ----------------
__device__ float g_h[TT*DD];
__device__ float g_cq[TT*QP];
__device__ float g_Q[TT*DD];
__device__ float g_ckv[TT*KVIN];
__device__ float g_kvl[TT*KVP];
__device__ float g_KV[TT*KVOUT];
__device__ float g_qq[BB*HH*SS*DH];
__device__ float g_kk[BB*HH*SS*DH];
__device__ float g_vv[BB*HH*SS*DH];
__device__ float g_o[TT*DD];
__device__ float g_h2[TT*DD];
__device__ float g_act[2*(size_t)TT*FF];     // shared: slice per n; routed: row per slot
__device__ float g_sc[2*TT*DD];              // shared expert outputs
__device__ float g_contrib[2*TT*DD];         // routed outputs per slot
__device__ int   g_cnt[EE];
__device__ int   g_tok[EE*TT];
__device__ int   g_cidx[EE*TT];
__device__ float g_wl[EE*TT];

__device__ __forceinline__ void mma_tf32(float c[4], const uint32_t a[4], const uint32_t b[2]) {
    asm volatile("mma.sync.aligned.m16n8k8.row.col.f32.tf32.tf32.f32 "
                 "{%0,%1,%2,%3}, {%4,%5,%6,%7}, {%8,%9}, {%0,%1,%2,%3};"
                 : "+f"(c[0]), "+f"(c[1]), "+f"(c[2]), "+f"(c[3])
                 : "r"(a[0]), "r"(a[1]), "r"(a[2]), "r"(a[3]), "r"(b[0]), "r"(b[1]));
}

__device__ __forceinline__ void cp_async16(float* smem_dst, const float* gmem_src, bool pred) {
    uint32_t s = (uint32_t)__cvta_generic_to_shared(smem_dst);
    int sz = pred ? 16 : 0;
    asm volatile("cp.async.cg.shared.global [%0], [%1], 16, %2;\n" :: "r"(s), "l"(gmem_src), "r"(sz));
}

// ---------------- block reduce helpers ----------------
__device__ __forceinline__ float block_reduce_sum(float v, float* sh) {
    __syncthreads();
    int lane = threadIdx.x & 31, wid = threadIdx.x >> 5;
    #pragma unroll
    for (int o = 16; o; o >>= 1) v += __shfl_down_sync(0xffffffffu, v, o);
    if (lane == 0) sh[wid] = v;
    __syncthreads();
    if (threadIdx.x == 0) {
        float r = 0.f;
        int nw = blockDim.x >> 5;
        for (int i = 0; i < nw; i++) r += sh[i];
        sh[0] = r;
    }
    __syncthreads();
    return sh[0];
}

// ---------------- LayerNorm ----------------
__global__ void ln_kernel(const float* __restrict__ x, const float* __restrict__ w,
                          const float* __restrict__ b, float* __restrict__ y,
                          int cols, int inStride, int outStride) {
    int row = blockIdx.x;
    const float* xi = x + (size_t)row * inStride;
    float* yo = y + (size_t)row * outStride;
    __shared__ float sh[8];
    int t = threadIdx.x;
    float s = 0.f;
    for (int j = t; j < cols; j += 256) s += xi[j];
    float mean = block_reduce_sum(s, sh) / (float)cols;
    float v = 0.f;
    for (int j = t; j < cols; j += 256) { float d = xi[j] - mean; v += d * d; }
    float var = block_reduce_sum(v, sh) / (float)cols;
    float rstd = rsqrtf(var + 1e-5f);
    for (int j = t; j < cols; j += 256) {
        float o = (xi[j] - mean) * rstd * w[j];
        if (b) o += b[j];
        yo[j] = o;
    }
}

// ---------------- pipelined TF32 tensor-core GEMM ----------------
// C[M,N] = A[M,K] @ B ; B is [K,N] (BisNT=0) or [N,K]^T (BisNT=1).
// blockIdx.z selects a sub-problem via strides (zsA/zsB/zsC in elements,
// zsL for the gather/scatter/scale lists; cntPtr advances by 1 per z).
__global__ void __launch_bounds__(256)
gemm_tf32(const float* __restrict__ A, const float* __restrict__ Bm, float* __restrict__ C,
          int M, int N, int K, int BisNT,
          const float* __restrict__ resid, int doGelu, int doAccum,
          const int* __restrict__ aRows, const int* __restrict__ cRows,
          const float* __restrict__ rowScale, const int* __restrict__ cntPtr,
          size_t zsA, size_t zsB, size_t zsC, int zsL) {
    extern __shared__ float smem[];
    int e = blockIdx.z;
    A  += (size_t)e * zsA;
    Bm += (size_t)e * zsB;
    C  += (size_t)e * zsC;
    if (aRows)    aRows    += (size_t)e * zsL;
    if (cRows)    cRows    += (size_t)e * zsL;
    if (rowScale) rowScale += (size_t)e * zsL;
    if (cntPtr)   cntPtr   += e;

    int Meff = M;
    if (cntPtr) { int c = *cntPtr; if (c < Meff) Meff = c; }
    int bm = blockIdx.y * BM, bn = blockIdx.x * BN;
    if (bm >= Meff) return;
    int t = threadIdx.x;
    int lane = t & 31, warp = t >> 5;
    int wm = warp & 1, wn = warp >> 1;       // 2 x 4 warp grid
    int g = lane >> 2, tg = lane & 3;

    const int NT = K / BK;

    // ---- async stage issue ----
    auto issue = [&](int kt) {
        int st = kt % NSTAGE;
        float* Sa = smem + st * STAGE_FLOATS;
        float* Sb = Sa + A_FLOATS;
        int k0 = kt * BK;
        #pragma unroll
        for (int i = 0; i < 4; i++) {
            int c = t + i * 256;
            int row = c >> 3, col4 = c & 7;
            int gm = bm + row;
            bool p = gm < Meff;
            int ar = p ? (aRows ? aRows[gm] : gm) : 0;
            cp_async16(Sa + row * 36 + col4 * 4, A + (size_t)ar * K + k0 + col4 * 4, p);
        }
        if (!BisNT) {
            #pragma unroll
            for (int i = 0; i < 4; i++) {
                int c = t + i * 256;
                int k = c >> 5, col4 = c & 31;
                bool p = (bn + col4 * 4) < N;
                cp_async16(Sb + k * 136 + col4 * 4, Bm + (size_t)(k0 + k) * N + bn + col4 * 4, p);
            }
        } else {
            #pragma unroll
            for (int i = 0; i < 4; i++) {
                int c = t + i * 256;
                int row = c >> 3, col4 = c & 7;
                bool p = (bn + row) < N;
                cp_async16(Sb + row * 36 + col4 * 4, Bm + (size_t)(bn + row) * K + k0 + col4 * 4, p);
            }
        }
        asm volatile("cp.async.commit_group;\n");
    };

    float acc[4][4][4];
    #pragma unroll
    for (int a = 0; a < 4; a++)
        #pragma unroll
        for (int b = 0; b < 4; b++)
            #pragma unroll
            for (int c = 0; c < 4; c++) acc[a][b][c] = 0.f;

    issue(0);
    if (NT > 1) issue(1);

    for (int kt = 0; kt < NT; kt++) {
        if (kt + 2 < NT) issue(kt + 2);
        // wait for tile kt (allow the later issues to stay in flight)
        if (kt + 2 < NT)      asm volatile("cp.async.wait_group 2;\n");
        else if (kt + 1 < NT) asm volatile("cp.async.wait_group 1;\n");
        else                  asm volatile("cp.async.wait_group 0;\n");
        __syncthreads();

        int st = kt % NSTAGE;
        const float* Sa = smem + st * STAGE_FLOATS;
        const float* Sb = Sa + A_FLOATS;
        const uint32_t* Sau = (const uint32_t*)Sa;
        const uint32_t* Sbu = (const uint32_t*)Sb;

        #pragma unroll
        for (int ks = 0; ks < 4; ks++) {
            int kb = ks * 8;
            uint32_t afr[4][4], bfr[4][2];
            #pragma unroll
            for (int mi = 0; mi < 4; mi++) {
                int mr = wm * 64 + mi * 16;
                afr[mi][0] = Sau[(mr + g) * 36 + kb + tg];
                afr[mi][1] = Sau[(mr + g + 8) * 36 + kb + tg];
                afr[mi][2] = Sau[(mr + g) * 36 + kb + tg + 4];
                afr[mi][3] = Sau[(mr + g + 8) * 36 + kb + tg + 4];
            }
            #pragma unroll
            for (int ni = 0; ni < 4; ni++) {
                int nc = wn * 32 + ni * 8;
                if (!BisNT) {
                    bfr[ni][0] = Sbu[(kb + tg) * 136 + nc + g];
                    bfr[ni][1] = Sbu[(kb + tg + 4) * 136 + nc + g];
                } else {
                    bfr[ni][0] = Sbu[(nc + g) * 36 + kb + tg];
                    bfr[ni][1] = Sbu[(nc + g) * 36 + kb + tg + 4];
                }
            }
            #pragma unroll
            for (int mi = 0; mi < 4; mi++)
                #pragma unroll
                for (int ni = 0; ni < 4; ni++)
                    mma_tf32(acc[mi][ni], afr[mi], bfr[ni]);
        }
        __syncthreads();   // protect stage reuse vs next issue
    }

    // --- epilogue ---
    #pragma unroll
    for (int mi = 0; mi < 4; mi++) {
        #pragma unroll
        for (int hh = 0; hh < 2; hh++) {
            int m = bm + wm * 64 + mi * 16 + g + hh * 8;
            if (m >= Meff) continue;
            float scale = rowScale ? rowScale[m] : 1.f;
            int crow = cRows ? cRows[m] : m;
            #pragma unroll
            for (int ni = 0; ni < 4; ni++) {
                #pragma unroll
                for (int jj = 0; jj < 2; jj++) {
                    int col = bn + wn * 32 + ni * 8 + tg * 2 + jj;
                    if (col >= N) continue;
                    float v = acc[mi][ni][hh * 2 + jj];
                    if (doGelu) v = 0.5f * v * (1.f + erff(v * 0.70710678118654752f));
                    v *= scale;
                    if (resid) v += resid[(size_t)m * N + col];
                    size_t oidx = (size_t)crow * N + col;
                    if (doAccum) C[oidx] += v; else C[oidx] = v;
                }
            }
        }
    }
}

// ---------------- build q/k/v with RoPE ----------------
__global__ void qkv_build() {
    int s = blockIdx.x, h = blockIdx.y, b = blockIdx.z, d = threadIdx.x;
    int i = b * SS + s;
    __shared__ float qr[32], kr[32];
    if (d < 32) {
        qr[d] = g_Q[(size_t)i * DD + h * DH + NOPE + d];
        kr[d] = g_ckv[(size_t)i * KVIN + KVP + d];
    }
    __syncthreads();
    float qv, kv;
    if (d < NOPE) {
        qv = g_Q[(size_t)i * DD + h * DH + d];
        kv = g_KV[(size_t)i * KVOUT + h * 96 + d];
    } else {
        int j = d - NOPE;
        int fi = j & 15;
        float ang = (float)s * expf(-(float)fi * (9.210340371976184f / 32.f));
        float c = cosf(ang), sn = sinf(ang);
        float qrot = (j < 16) ? -qr[j + 16] : qr[j - 16];
        float krot = (j < 16) ? -kr[j + 16] : kr[j - 16];
        qv = qr[j] * c + qrot * sn;
        kv = kr[j] * c + krot * sn;
    }
    size_t o = (((size_t)b * HH + h) * SS + s) * DH + d;
    g_qq[o] = qv;
    g_kk[o] = kv;
    g_vv[o] = g_KV[(size_t)i * KVOUT + h * 96 + NOPE + d];
}

// ---------------- flash attention: 64 queries per block ----------------
__global__ void __launch_bounds__(256) flash_attn() {
    int qt = blockIdx.x, h = blockIdx.y, b = blockIdx.z;
    int t = threadIdx.x;
    int tx = t & 15, ty = t >> 4;
    __shared__ float Qst[64][64];    // [d][m], pre-scaled
    __shared__ float KP[64][72];     // Kst [d][n]  -> then Ps [m][kk]
    const size_t bh = ((size_t)b * HH + h) * SS;
    const float* qg = g_qq + (bh + (size_t)qt * 64) * DH;
    {
        int m = t & 63, c0 = t >> 6;
        #pragma unroll
        for (int it = 0; it < 4; it++) {
            int d4 = c0 + it * 4;
            float4 v = *(const float4*)(qg + (size_t)m * DH + d4 * 4);
            Qst[d4 * 4 + 0][m] = v.x * 0.125f;
            Qst[d4 * 4 + 1][m] = v.y * 0.125f;
            Qst[d4 * 4 + 2][m] = v.z * 0.125f;
            Qst[d4 * 4 + 3][m] = v.w * 0.125f;
        }
    }
    float accO[4][4];
    float rowM[4], rowL[4];
    #pragma unroll
    for (int i = 0; i < 4; i++) {
        rowM[i] = -1e30f; rowL[i] = 0.f;
        #pragma unroll
        for (int j = 0; j < 4; j++) accO[i][j] = 0.f;
    }
    for (int kt = 0; kt <= qt; kt++) {
        const float* kg = g_kk + (bh + (size_t)kt * 64) * DH;
        __syncthreads();
        {
            int n = t & 63, c0 = t >> 6;
            #pragma unroll
            for (int it = 0; it < 4; it++) {
                int d4 = c0 + it * 4;
                float4 v = *(const float4*)(kg + (size_t)n * DH + d4 * 4);
                KP[d4 * 4 + 0][n] = v.x;
                KP[d4 * 4 + 1][n] = v.y;
                KP[d4 * 4 + 2][n] = v.z;
                KP[d4 * 4 + 3][n] = v.w;
            }
        }
        __syncthreads();
        float s[4][4];
        #pragma unroll
        for (int i = 0; i < 4; i++)
            #pragma unroll
            for (int j = 0; j < 4; j++) s[i][j] = 0.f;
        #pragma unroll 8
        for (int d = 0; d < 64; d++) {
            float4 qa = *(const float4*)&Qst[d][ty * 4];
            float4 kb = *(const float4*)&KP[d][tx * 4];
            float aa[4] = {qa.x, qa.y, qa.z, qa.w};
            float bb[4] = {kb.x, kb.y, kb.z, kb.w};
            #pragma unroll
            for (int i = 0; i < 4; i++)
                #pragma unroll
                for (int j = 0; j < 4; j++) s[i][j] += aa[i] * bb[j];
        }
        if (kt == qt) {
            #pragma unroll
            for (int i = 0; i < 4; i++)
                #pragma unroll
                for (int j = 0; j < 4; j++)
                    if (tx * 4 + j > ty * 4 + i) s[i][j] = -1e30f;
        }
        float ps[4][4];
        #pragma unroll
        for (int i = 0; i < 4; i++) {
            float tm = fmaxf(fmaxf(s[i][0], s[i][1]), fmaxf(s[i][2], s[i][3]));
            #pragma unroll
            for (int o = 8; o; o >>= 1) tm = fmaxf(tm, __shfl_xor_sync(0xffffffffu, tm, o, 16));
            float nm = fmaxf(rowM[i], tm);
            float corr = __expf(rowM[i] - nm);
            rowM[i] = nm;
            float rs = 0.f;
            #pragma unroll
            for (int j = 0; j < 4; j++) { ps[i][j] = __expf(s[i][j] - nm); rs += ps[i][j]; }
            #pragma unroll
            for (int o = 8; o; o >>= 1) rs += __shfl_xor_sync(0xffffffffu, rs, o, 16);
            rowL[i] = rowL[i] * corr + rs;
            #pragma unroll
            for (int j = 0; j < 4; j++) accO[i][j] *= corr;
        }
        __syncthreads();
        #pragma unroll
        for (int i = 0; i < 4; i++)
            *(float4*)&KP[ty * 4 + i][tx * 4] = make_float4(ps[i][0], ps[i][1], ps[i][2], ps[i][3]);
        __syncthreads();
        const float* vg = g_vv + (bh + (size_t)kt * 64) * DH;
        #pragma unroll 4
        for (int k4 = 0; k4 < 16; k4++) {
            float pav[4][4];
            #pragma unroll
            for (int i = 0; i < 4; i++)
                *(float4*)pav[i] = *(const float4*)&KP[ty * 4 + i][k4 * 4];
            #pragma unroll
            for (int kk = 0; kk < 4; kk++) {
                float4 vb = *(const float4*)(vg + (size_t)(k4 * 4 + kk) * DH + tx * 4);
                float bb[4] = {vb.x, vb.y, vb.z, vb.w};
                #pragma unroll
                for (int i = 0; i < 4; i++)
                    #pragma unroll
                    for (int j = 0; j < 4; j++) accO[i][j] += pav[i][kk] * bb[j];
            }
        }
    }
    #pragma unroll
    for (int i = 0; i < 4; i++) {
        float inv = 1.f / rowL[i];
        int m = qt * 64 + ty * 4 + i;
        float* op = g_o + ((size_t)(b * SS + m)) * DD + h * DH + tx * 4;
        op[0] = accO[i][0] * inv;
        op[1] = accO[i][1] * inv;
        op[2] = accO[i][2] * inv;
        op[3] = accO[i][3] * inv;
    }
}

// ---------------- routing ----------------
__global__ void zero_cnt_kernel() {
    if (threadIdx.x < EE) g_cnt[threadIdx.x] = 0;
}

__global__ void route_kernel(const float* __restrict__ h2, const float* __restrict__ cent,
                             const float* __restrict__ rbias) {
    int warp = threadIdx.x >> 5, lane = threadIdx.x & 31;
    int tok = blockIdx.x * 8 + warp;
    if (tok >= TT) return;
    const float* hp = h2 + (size_t)tok * DD;
    float raw[EE];
    #pragma unroll
    for (int e = 0; e < EE; e++) {
        const float* cp = cent + e * DD;
        float s = 0.f;
        for (int j = lane; j < DD; j += 32) s += hp[j] * cp[j];
        #pragma unroll
        for (int o = 16; o; o >>= 1) s += __shfl_down_sync(0xffffffffu, s, o);
        raw[e] = __shfl_sync(0xffffffffu, s, 0);
    }
    if (lane == 0) {
        int e0 = 0;
        float b0 = raw[0] + rbias[0];
        for (int e = 1; e < EE; e++) {
            float v = raw[e] + rbias[e];
            if (v > b0) { b0 = v; e0 = e; }
        }
        int e1 = -1;
        float b1 = -3.4e38f;
        for (int e = 0; e < EE; e++) {
            if (e == e0) continue;
            float v = raw[e] + rbias[e];
            if (v > b1) { b1 = v; e1 = e; }
        }
        float w0 = 1.f / (1.f + expf(-raw[e0]));
        float w1 = 1.f / (1.f + expf(-raw[e1]));
        float inv = 1.f / (w0 + w1 + 1e-9f);
        w0 *= inv; w1 *= inv;
        int p0 = atomicAdd(&g_cnt[e0], 1);
        g_tok[e0 * TT + p0] = tok;
        g_cidx[e0 * TT + p0] = tok;
        g_wl[e0 * TT + p0] = w0;
        int p1 = atomicAdd(&g_cnt[e1], 1);
        g_tok[e1 * TT + p1] = tok;
        g_cidx[e1 * TT + p1] = TT + tok;
        g_wl[e1 * TT + p1] = w1;
    }
}

// ---------------- final: out += sc0 + sc1 + contrib0 + contrib1 ----------------
__global__ void final_add_kernel(float* __restrict__ out) {
    int idx = blockIdx.x * blockDim.x + threadIdx.x;
    if (idx < TT * DD)
        out[idx] += g_sc[idx] + g_sc[(size_t)TT * DD + idx]
                  + g_contrib[idx] + g_contrib[(size_t)TT * DD + idx];
}

// ---------------- launch ----------------
static inline dim3 ggrid(int M, int N, int Z = 1) {
    return dim3((N + BN - 1) / BN, (M + BM - 1) / BM, Z);
}

extern "C" void kernel_launch(void* const* d_in, const int* in_sizes, int n_in,
                              void* d_out, int out_size) {
    const float* x        = (const float*)d_in[0];
    const float* ln1_w    = (const float*)d_in[1];
    const float* ln2_w    = (const float*)d_in[2];
    const float* W_dq     = (const float*)d_in[3];
    const float* W_uq     = (const float*)d_in[4];
    const float* q_ln_w   = (const float*)d_in[5];
    const float* q_ln_b   = (const float*)d_in[6];
    const float* W_dkv    = (const float*)d_in[7];
    const float* W_ukv    = (const float*)d_in[8];
    const float* kv_ln_w  = (const float*)d_in[9];
    const float* kv_ln_b  = (const float*)d_in[10];
    const float* W_o      = (const float*)d_in[11];
    const float* s_fc     = (const float*)d_in[12];
    const float* s_proj   = (const float*)d_in[13];
    const float* e_fc     = (const float*)d_in[14];
    const float* e_proj   = (const float*)d_in[15];
    const float* centroids= (const float*)d_in[16];
    const float* rbias    = (const float*)d_in[17];
    float* out = (float*)d_out;

    cudaFuncSetAttribute(gemm_tf32, cudaFuncAttributeMaxDynamicSharedMemorySize, SMEM_BYTES);

    float *ph, *pcq, *pQ, *pckv, *pkvl, *pKV, *po, *ph2, *pact, *psc, *pcontrib, *pwl;
    int *pcnt, *ptok, *pcidx;
    cudaGetSymbolAddress((void**)&ph, g_h);
    cudaGetSymbolAddress((void**)&pcq, g_cq);
    cudaGetSymbolAddress((void**)&pQ, g_Q);
    cudaGetSymbolAddress((void**)&pckv, g_ckv);
    cudaGetSymbolAddress((void**)&pkvl, g_kvl);
    cudaGetSymbolAddress((void**)&pKV, g_KV);
    cudaGetSymbolAddress((void**)&po, g_o);
    cudaGetSymbolAddress((void**)&ph2, g_h2);
    cudaGetSymbolAddress((void**)&pact, g_act);
    cudaGetSymbolAddress((void**)&psc, g_sc);
    cudaGetSymbolAddress((void**)&pcontrib, g_contrib);
    cudaGetSymbolAddress((void**)&pwl, g_wl);
    cudaGetSymbolAddress((void**)&pcnt, g_cnt);
    cudaGetSymbolAddress((void**)&ptok, g_tok);
    cudaGetSymbolAddress((void**)&pcidx, g_cidx);

    // 1) h = LN1(x)
    ln_kernel<<<TT, 256>>>(x, ln1_w, nullptr, ph, DD, DD, DD);
    // 2) cq = LN_q(h @ W_dq)
    gemm_tf32<<<ggrid(TT, QP), 256, SMEM_BYTES>>>(ph, W_dq, pcq, TT, QP, DD, 0,
        nullptr, 0, 0, nullptr, nullptr, nullptr, nullptr, 0, 0, 0, 0);
    ln_kernel<<<TT, 256>>>(pcq, q_ln_w, q_ln_b, pcq, QP, QP, QP);
    // 3) Q = cq @ W_uq
    gemm_tf32<<<ggrid(TT, DD), 256, SMEM_BYTES>>>(pcq, W_uq, pQ, TT, DD, QP, 0,
        nullptr, 0, 0, nullptr, nullptr, nullptr, nullptr, 0, 0, 0, 0);
    // 4) ckv = h @ W_dkv ; kv_lora = LN_kv(ckv[:, :512])
    gemm_tf32<<<ggrid(TT, KVIN), 256, SMEM_BYTES>>>(ph, W_dkv, pckv, TT, KVIN, DD, 0,
        nullptr, 0, 0, nullptr, nullptr, nullptr, nullptr, 0, 0, 0, 0);
    ln_kernel<<<TT, 256>>>(pckv, kv_ln_w, kv_ln_b, pkvl, KVP, KVIN, KVP);
    // 5) KV = kv_lora @ W_ukv
    gemm_tf32<<<ggrid(TT, KVOUT), 256, SMEM_BYTES>>>(pkvl, W_ukv, pKV, TT, KVOUT, KVP, 0,
        nullptr, 0, 0, nullptr, nullptr, nullptr, nullptr, 0, 0, 0, 0);
    // 6) q/k/v with RoPE
    qkv_build<<<dim3(SS, HH, BB), 64>>>();
    // 7) flash attention -> g_o
    flash_attn<<<dim3(SS / 64, HH, BB), 256>>>();
    // 8) out = x + o @ W_o^T
    gemm_tf32<<<ggrid(TT, DD), 256, SMEM_BYTES>>>(po, W_o, out, TT, DD, DD, 1,
        x, 0, 0, nullptr, nullptr, nullptr, nullptr, 0, 0, 0, 0);
    // 9) h2 = LN2(out)
    ln_kernel<<<TT, 256>>>(out, ln2_w, nullptr, ph2, DD, DD, DD);
    // 10) routing
    zero_cnt_kernel<<<1, 32>>>();
    route_kernel<<<(TT + 7) / 8, 256>>>(ph2, centroids, rbias);
    // 11) shared experts, batched over z=2:
    //     act[n] = gelu(h2 @ s_fc[n]^T) ; sc[n] = act[n] @ s_proj[n]^T
    gemm_tf32<<<ggrid(TT, FF, NS), 256, SMEM_BYTES>>>(ph2, s_fc, pact, TT, FF, DD, 1,
        nullptr, 1, 0, nullptr, nullptr, nullptr, nullptr,
        0, (size_t)FF * DD, (size_t)TT * FF, 0);
    gemm_tf32<<<ggrid(TT, DD, NS), 256, SMEM_BYTES>>>(pact, s_proj, psc, TT, DD, FF, 1,
        nullptr, 0, 0, nullptr, nullptr, nullptr, nullptr,
        (size_t)TT * FF, (size_t)DD * FF, (size_t)TT * DD, 0);
    // 12) routed experts, batched over z=8 (count-bounded):
    //     act[slot] = gelu(h2[tok] @ e_fc[e]^T) ; contrib[slot] = w * act[slot] @ e_proj[e]^T
    gemm_tf32<<<ggrid(TT, FF, EE), 256, SMEM_BYTES>>>(ph2, e_fc, pact, TT, FF, DD, 1,
        nullptr, 1, 0, ptok, pcidx, nullptr, pcnt,
        0, (size_t)FF * DD, 0, TT);
    gemm_tf32<<<ggrid(TT, DD, EE), 256, SMEM_BYTES>>>(pact, e_proj, pcontrib, TT, DD, FF, 1,
        nullptr, 0, 0, pcidx, pcidx, pwl, pcnt,
        0, (size_t)DD * FF, 0, TT);
    // 13) out += sc0 + sc1 + contrib0 + contrib1
    final_add_kernel<<<(TT * DD + 255) / 256, 256>>>(out);
}